// round 12
// baseline (speedup 1.0000x reference)
#include <cuda_runtime.h>
#include <cuda_bf16.h>
#include <cstdint>

#define N_PTS   131072
#define K_CB    1024
#define D_DIM   10
#define TILE    128              // points per CTA-tile
#define NTILE   (N_PTS / TILE)   // 1024
#define GRID    148
#define THREADS 256              // 8 warps
#define NCB     (K_CB / 8)       // 128 code-blocks of 8
#define EPS     0.02f
#define BIGF    3.402823466e+38f

// dynamic smem offsets (bytes)
#define OFF_SX   0               // 128 x 10 fp32 x-tile          (5120)
#define OFF_EF   5120            // 1024 x 10 fp32 codebook       (40960)
#define OFF_ESQ  46080           // 1024 fp32 esq                 (4096)
#define OFF_B    50176           // B frags: 128cb x 2split x 32lane x 8B (65536)
#define OFF_RED  115712          // 8 warp partials
#define OFF_LAST 115744
#define SMEM_TOTAL 115760

__device__ float        g_partials[GRID];
__device__ unsigned int g_done = 0;

__device__ __forceinline__ uint32_t pk(float lo, float hi) {
    uint32_t r;
    asm("cvt.rn.bf16x2.f32 %0, %1, %2;" : "=r"(r) : "f"(hi), "f"(lo));
    return r;
}
__device__ __forceinline__ float rl(float v) {   // residual after bf16 hi
    return v - __bfloat162float(__float2bfloat16_rn(v));
}
__device__ __forceinline__ void mma(float c[4], const uint32_t a[4],
                                    uint32_t b0, uint32_t b1) {
    asm volatile(
        "mma.sync.aligned.m16n8k16.row.col.f32.bf16.bf16.f32 "
        "{%0,%1,%2,%3}, {%4,%5,%6,%7}, {%8,%9}, {%0,%1,%2,%3};"
        : "+f"(c[0]), "+f"(c[1]), "+f"(c[2]), "+f"(c[3])
        : "r"(a[0]), "r"(a[1]), "r"(a[2]), "r"(a[3]), "r"(b0), "r"(b1));
}

// top-2 update, strict < keeps first index (codes processed ascending)
__device__ __forceinline__ void upd(float v, int i, float& b1v, int& b1i,
                                    float& b2v, int& b2i) {
    if (v < b1v) { b2v = b1v; b2i = b1i; b1v = v; b1i = i; }
    else if (v < b2v) { b2v = v; b2i = i; }
}
// merge other thread's top-2 (index tiebreak)
__device__ __forceinline__ void mergeS(float& b1v, int& b1i, float& b2v, int& b2i,
                                       float o1v, int o1i, float o2v, int o2i) {
    bool t1 = (o1v < b1v) || (o1v == b1v && o1i < b1i);
    if (t1) {
        bool t2 = (b1v < o2v) || (b1v == o2v && b1i < o2i);
        float nb2v = t2 ? b1v : o2v; int nb2i = t2 ? b1i : o2i;
        b1v = o1v; b1i = o1i; b2v = nb2v; b2i = nb2i;
    } else {
        bool t3 = (o1v < b2v) || (o1v == b2v && o1i < b2i);
        if (t3) { b2v = o1v; b2i = o1i; }
    }
}

__global__ void __launch_bounds__(THREADS, 1)
vq_mma_kernel(const float* __restrict__ x,   // [N, D]
              const float* __restrict__ E,   // [K, D]
              float* __restrict__ out)       // [N*D] + loss slot
{
    extern __shared__ __align__(16) unsigned char smem[];
    float*    sX   = (float*)(smem + OFF_SX);
    float*    sEf  = (float*)(smem + OFF_EF);
    float*    sEsq = (float*)(smem + OFF_ESQ);
    uint32_t* sB   = (uint32_t*)(smem + OFF_B);
    float*    sred = (float*)(smem + OFF_RED);
    int*      s_last = (int*)(smem + OFF_LAST);

    const int tid  = threadIdx.x;
    const int bid  = blockIdx.x;
    const int w    = tid >> 5;
    const int lane = tid & 31;
    const int g    = lane >> 2;      // fragment group 0..7
    const int tg   = lane & 3;       // thread-in-group

    // ---- prologue: codebook fp32 + esq ----
    for (int i = tid; i < K_CB * D_DIM; i += THREADS) sEf[i] = E[i];
    __syncthreads();
    for (int k = tid; k < K_CB; k += THREADS) {
        float s = 0.f;
        #pragma unroll
        for (int j = 0; j < D_DIM; j++) {
            float e = sEf[k * D_DIM + j];
            s = fmaf(e, e, s);
        }
        sEsq[k] = s;
    }
    __syncthreads();

    // ---- prologue: B fragments (hi/lo splits of y=-2e, col10=esq) ----
    // fragment layout m16n8k16 B (col n = g): reg0={B[2tg][n],B[2tg+1][n]},
    // reg1={B[2tg+8][n],B[2tg+9][n]}. warp w fills cbs [w*16, w*16+16).
    for (int i = 0; i < 32; i++) {
        int cb = (w << 4) + (i >> 1);
        int s  = i & 1;
        int code = (cb << 3) + g;
        float v[4];
        #pragma unroll
        for (int e4 = 0; e4 < 4; e4++) {
            int k = 2 * tg + (e4 & 1) + ((e4 >> 1) << 3);  // 2tg,2tg+1,2tg+8,2tg+9
            float vv;
            if (k < D_DIM)       vv = -2.f * sEf[code * D_DIM + k];
            else if (k == D_DIM) vv = sEsq[code];
            else                 vv = 0.f;
            v[e4] = (s == 0) ? vv : rl(vv);
        }
        uint32_t* dst = sB + (((size_t)(cb * 2 + s)) * 32 + lane) * 2;
        dst[0] = pk(v[0], v[1]);
        dst[1] = pk(v[2], v[3]);
    }
    __syncthreads();

    float part = 0.f;

    for (int t = bid; t < NTILE; t += GRID) {
        // stage x tile (128 x 10 fp32, coalesced)
        {
            const float* xb = x + (size_t)t * TILE * D_DIM;
            for (int i = tid; i < TILE * D_DIM; i += THREADS) sX[i] = xb[i];
        }
        __syncthreads();

        // ---- A fragments: rows rA=w*16+g, rB=rA+8; cols 2tg,2tg+1,2tg+8,2tg+9
        const int rA = (w << 4) + g, rB = rA + 8;
        float xv[8];
        #pragma unroll
        for (int e4 = 0; e4 < 8; e4++) {
            int r = (e4 & 1) ? rB : rA;        // pair order below fixes mapping
            (void)r;
            xv[e4] = 0.f;
        }
        {
            int c0 = 2 * tg;
            #pragma unroll
            for (int half = 0; half < 2; half++) {      // k-lo / k-hi
                #pragma unroll
                for (int rr = 0; rr < 2; rr++) {        // rA / rB
                    int row = rr ? rB : rA;
                    #pragma unroll
                    for (int cc = 0; cc < 2; cc++) {
                        int c = c0 + cc + half * 8;
                        float vv = (c < D_DIM) ? sX[row * D_DIM + c]
                                               : ((c == D_DIM) ? 1.f : 0.f);
                        xv[half * 4 + rr * 2 + cc] = vv;
                    }
                }
            }
        }
        uint32_t Ah[4], Al[4];
        // reg order: a0={rA,k-lo}, a1={rB,k-lo}, a2={rA,k-hi}, a3={rB,k-hi}
        Ah[0] = pk(xv[0], xv[1]);  Al[0] = pk(rl(xv[0]), rl(xv[1]));
        Ah[1] = pk(xv[2], xv[3]);  Al[1] = pk(rl(xv[2]), rl(xv[3]));
        Ah[2] = pk(xv[4], xv[5]);  Al[2] = pk(rl(xv[4]), rl(xv[5]));
        Ah[3] = pk(xv[6], xv[7]);  Al[3] = pk(rl(xv[6]), rl(xv[7]));

        // ---- screening: 2 code-blocks per iter, top-2 tracking per point ----
        float b1vA = BIGF, b2vA = BIGF, b1vB = BIGF, b2vB = BIGF;
        int   b1iA = 0, b2iA = 0, b1iB = 0, b2iB = 0;

        for (int cb = 0; cb < NCB; cb += 2) {
            const uint32_t* p0 = sB + (((size_t)(cb * 2)) * 32 + lane) * 2;
            uint32_t bh00 = p0[0],      bh01 = p0[1];
            uint32_t bl00 = p0[64],     bl01 = p0[65];       // +1 split = +32 lanes*2
            uint32_t bh10 = p0[128],    bh11 = p0[129];      // cb+1 hi
            uint32_t bl10 = p0[192],    bl11 = p0[193];      // cb+1 lo

            float c0[4] = {0.f, 0.f, 0.f, 0.f};
            float c1[4] = {0.f, 0.f, 0.f, 0.f};
            mma(c0, Ah, bh00, bh01);
            mma(c0, Ah, bl00, bl01);
            mma(c0, Al, bh00, bh01);
            mma(c1, Ah, bh10, bh11);
            mma(c1, Ah, bl10, bl11);
            mma(c1, Al, bh10, bh11);

            const int k0 = (cb << 3) + 2 * tg;
            // point A: c0[0],c0[1] = codes k0,k0+1 ; c1[0],c1[1] = k0+8,k0+9
            float mA = fminf(fminf(c0[0], c0[1]), fminf(c1[0], c1[1]));
            if (mA < b2vA) {
                upd(c0[0], k0,     b1vA, b1iA, b2vA, b2iA);
                upd(c0[1], k0 + 1, b1vA, b1iA, b2vA, b2iA);
                upd(c1[0], k0 + 8, b1vA, b1iA, b2vA, b2iA);
                upd(c1[1], k0 + 9, b1vA, b1iA, b2vA, b2iA);
            }
            float mB = fminf(fminf(c0[2], c0[3]), fminf(c1[2], c1[3]));
            if (mB < b2vB) {
                upd(c0[2], k0,     b1vB, b1iB, b2vB, b2iB);
                upd(c0[3], k0 + 1, b1vB, b1iB, b2vB, b2iB);
                upd(c1[2], k0 + 8, b1vB, b1iB, b2vB, b2iB);
                upd(c1[3], k0 + 9, b1vB, b1iB, b2vB, b2iB);
            }
        }

        // ---- merge top-2 across the 4 lanes of each fragment group ----
        #pragma unroll
        for (int off = 1; off <= 2; off <<= 1) {
            float o1v = __shfl_down_sync(0xFFFFFFFFu, b1vA, off);
            int   o1i = __shfl_down_sync(0xFFFFFFFFu, b1iA, off);
            float o2v = __shfl_down_sync(0xFFFFFFFFu, b2vA, off);
            int   o2i = __shfl_down_sync(0xFFFFFFFFu, b2iA, off);
            mergeS(b1vA, b1iA, b2vA, b2iA, o1v, o1i, o2v, o2i);
            o1v = __shfl_down_sync(0xFFFFFFFFu, b1vB, off);
            o1i = __shfl_down_sync(0xFFFFFFFFu, b1iB, off);
            o2v = __shfl_down_sync(0xFFFFFFFFu, b2vB, off);
            o2i = __shfl_down_sync(0xFFFFFFFFu, b2iB, off);
            mergeS(b1vB, b1iB, b2vB, b2iB, o1v, o1i, o2v, o2i);
        }

        // ---- exact refine + output (owner lanes tg==0; 2 points each) ----
        if (tg == 0) {
            #pragma unroll
            for (int pp = 0; pp < 2; pp++) {
                int row = pp ? rB : rA;
                float b1v = pp ? b1vB : b1vA, b2v = pp ? b2vB : b2vA;
                int   b1i = pp ? b1iB : b1iA, b2i = pp ? b2iB : b2iA;
                const float* xr = sX + row * D_DIM;

                float s1 = 0.f, s2 = 0.f;
                #pragma unroll
                for (int j = 0; j < D_DIM; j++) {
                    s1 = fmaf(xr[j], sEf[b1i * D_DIM + j], s1);
                    s2 = fmaf(xr[j], sEf[b2i * D_DIM + j], s2);
                }
                float d1 = fmaf(-2.f, s1, sEsq[b1i]);
                float d2 = fmaf(-2.f, s2, sEsq[b2i]);
                bool sw = (d2 < d1) || (d2 == d1 && b2i < b1i);
                int   kw = sw ? b2i : b1i;
                float dw = sw ? d2 : d1;
                (void)b1v;

                if (!(dw < b2v - EPS)) {
                    // rare: margin unsafe -> exact full scan (first-min)
                    dw = BIGF; kw = 0;
                    for (int k = 0; k < K_CB; k++) {
                        float s = 0.f;
                        #pragma unroll
                        for (int j = 0; j < D_DIM; j++)
                            s = fmaf(xr[j], sEf[k * D_DIM + j], s);
                        float d = fmaf(-2.f, s, sEsq[k]);
                        if (d < dw) { dw = d; kw = k; }
                    }
                }

                const float* er = sEf + kw * D_DIM;
                float* o = out + ((size_t)t * TILE + row) * D_DIM;
                #pragma unroll
                for (int j = 0; j < D_DIM; j++) {
                    float qv = er[j];
                    o[j] = qv;
                    float dd = xr[j] - qv;
                    part = fmaf(dd, dd, part);
                }
            }
        }
        __syncthreads();   // protect sX before next tile restage
    }

    // ---- deterministic loss reduction ----
    #pragma unroll
    for (int off = 16; off > 0; off >>= 1)
        part += __shfl_down_sync(0xFFFFFFFFu, part, off);
    if (lane == 0) sred[w] = part;
    __syncthreads();

    if (tid == 0) {
        float s = 0.f;
        #pragma unroll
        for (int i = 0; i < THREADS / 32; i++) s += sred[i];
        g_partials[bid] = s;
        __threadfence();
        unsigned int old = atomicAdd(&g_done, 1u);
        *s_last = (old == GRID - 1) ? 1 : 0;
    }
    __syncthreads();

    if (*s_last) {
        float* sfin = sX;   // reuse staging area
        float s = 0.f;
        for (int r = tid; r < GRID; r += THREADS) s += g_partials[r];
        sfin[tid] = s;
        __syncthreads();
        #pragma unroll
        for (int o = THREADS / 2; o > 0; o >>= 1) {
            if (tid < o) sfin[tid] += sfin[tid + o];
            __syncthreads();
        }
        if (tid == 0) {
            out[(size_t)N_PTS * D_DIM] = sfin[0] * (1.0f / ((float)N_PTS * (float)D_DIM));
            g_done = 0;   // reset for graph replay
        }
    }
}

extern "C" void kernel_launch(void* const* d_in, const int* in_sizes, int n_in,
                              void* d_out, int out_size) {
    const float* x = (const float*)d_in[0];   // encoder_embedding [N, D]
    const float* E = (const float*)d_in[1];   // embedding_weight  [K, D]
    float* out = (float*)d_out;

    cudaFuncSetAttribute(vq_mma_kernel,
                         cudaFuncAttributeMaxDynamicSharedMemorySize, SMEM_TOTAL);
    vq_mma_kernel<<<GRID, THREADS, SMEM_TOTAL>>>(x, E, out);
}

// round 13
// speedup vs baseline: 5.3021x; 5.3021x over previous
#include <cuda_runtime.h>

#define N_PTS   131072
#define K_CB    1024
#define NPAIR   512          // K_CB / 2
#define HALFP   256          // pairs per half-scan
#define D_DIM   10
#define PROW    20           // floats per code-pair row: 10 dims x f32x2
#define THREADS 128
#define NSM     148
#define GRID    (NSM * 4)    // 592 CTAs, 4/SM -> 16 warps/SM = 4 per SMSP
#define NSETS   (GRID * 2)   // 1184 point-sets (one per warp-pair)
#define WTILES  (N_PTS / 32) // 4096 warp-tiles of 32 points
#define S4      (WTILES - 3 * NSETS)   // 544 sets take 4 tiles, rest 3

__device__ float        g_partials[GRID];
__device__ unsigned int g_done = 0;

__device__ __forceinline__ unsigned long long fma2(
    unsigned long long a, unsigned long long b, unsigned long long c) {
    unsigned long long d;
    asm("fma.rn.f32x2 %0, %1, %2, %3;" : "=l"(d) : "l"(a), "l"(b), "l"(c));
    return d;
}
__device__ __forceinline__ unsigned long long dup2(float v) {
    unsigned long long r;
    asm("mov.b64 %0, {%1, %1};" : "=l"(r) : "f"(v));
    return r;
}
__device__ __forceinline__ void unpack2(unsigned long long v, float& lo, float& hi) {
    asm("mov.b64 {%0, %1}, %2;" : "=f"(lo), "=f"(hi) : "l"(v));
}

// Bit-exact distance pair for one code-pair row (same FMA order as hot loop).
__device__ __forceinline__ void pair_dists(const ulonglong2* w,
                                           unsigned long long esq,
                                           const unsigned long long* xd,
                                           float& d0, float& d1) {
    ulonglong2 c0 = w[0], c1 = w[1], c2 = w[2], c3 = w[3], c4 = w[4];
    unsigned long long a = esq;
    a = fma2(c0.x, xd[0], a);
    a = fma2(c0.y, xd[1], a);
    a = fma2(c1.x, xd[2], a);
    a = fma2(c1.y, xd[3], a);
    a = fma2(c2.x, xd[4], a);
    a = fma2(c2.y, xd[5], a);
    a = fma2(c3.x, xd[6], a);
    a = fma2(c3.y, xd[7], a);
    a = fma2(c4.x, xd[8], a);
    a = fma2(c4.y, xd[9], a);
    unpack2(a, d0, d1);
}

__global__ void __launch_bounds__(THREADS, 4)
vq_kernel(const float* __restrict__ x,      // [N, D]
          const float* __restrict__ E,      // [K, D]
          float* __restrict__ out)          // [N*D] quantized + loss slot
{
    __shared__ float sE[NPAIR * PROW];      // 40960 B pair-packed dims (f32x2 layout)
    __shared__ float sEsq[K_CB];            //  4096 B (esq0,esq1) adjacent pairs
    __shared__ float sMm[2][4][32];         // half-1 best m   per set/tile/lane
    __shared__ int   sMb[2][4][32];         // half-1 best pair index
    __shared__ float sred[THREADS / 32];
    __shared__ int   s_last;

    const int tid  = threadIdx.x;
    const int bid  = blockIdx.x;
    const int wid  = tid >> 5;              // 0..3
    const int lane = tid & 31;
    const int setl = wid >> 1;              // set within CTA: 0,1
    const int half = wid & 1;               // 0: pairs [0,256), 1: [256,512)

    // --- codebook -> pair-packed shared: sE[p*20 + 2j + l] = E[(2p+l)*10 + j] ---
    for (int i = tid; i < K_CB * D_DIM; i += THREADS) {
        int k = i / D_DIM;
        int j = i - k * D_DIM;
        sE[(k >> 1) * PROW + 2 * j + (k & 1)] = E[i];
    }
    __syncthreads();
    for (int k = tid; k < K_CB; k += THREADS) {
        int p = k >> 1, l = k & 1;
        float s = 0.f;
        #pragma unroll
        for (int j = 0; j < D_DIM; j++) {
            float v = sE[p * PROW + 2 * j + l];
            s += v * v;
        }
        sEsq[k] = s;
    }
    __syncthreads();

    // --- set assignment: global set id -> 4 or 3 warp-tiles of 32 points ---
    const int sg = bid * 2 + setl;
    int wt0, cnt;
    if (sg < S4) { cnt = 4; wt0 = sg * 4; }
    else         { cnt = 3; wt0 = S4 * 4 + (sg - S4) * 3; }
    const int pstart = half * HALFP;

    // --- load this warp's points (both halves of a pair load the same points) ---
    unsigned long long xd[4][D_DIM];
    #pragma unroll
    for (int q = 0; q < 4; q++) {
        if (q < cnt) {
            const float* xp = x + (size_t)((wt0 + q) * 32 + lane) * D_DIM;
            #pragma unroll
            for (int j = 0; j < D_DIM; j++)
                xd[q][j] = dup2(-2.f * xp[j]);
        }
    }

    float best[4] = {3.402823466e+38f, 3.402823466e+38f,
                     3.402823466e+38f, 3.402823466e+38f};
    int   bp[4]   = {pstart, pstart, pstart, pstart};

    const ulonglong2* dims = (const ulonglong2*)sE;          // 5 per pair row
    const unsigned long long* esqp = (const unsigned long long*)sEsq;

    // --- half-codebook scan: 256 pairs, PPT-chained FMA (TLP hides LDS) ---
    #pragma unroll 2
    for (int i = 0; i < HALFP; ++i) {
        const int p = pstart + i;
        const ulonglong2* w = dims + (size_t)p * 5;
        ulonglong2 c0 = w[0], c1 = w[1], c2 = w[2], c3 = w[3], c4 = w[4];
        unsigned long long esq = esqp[p];

        #pragma unroll
        for (int q = 0; q < 4; q++) {
            if (q < cnt) {
                unsigned long long a = esq;
                a = fma2(c0.x, xd[q][0], a);
                a = fma2(c0.y, xd[q][1], a);
                a = fma2(c1.x, xd[q][2], a);
                a = fma2(c1.y, xd[q][3], a);
                a = fma2(c2.x, xd[q][4], a);
                a = fma2(c2.y, xd[q][5], a);
                a = fma2(c3.x, xd[q][6], a);
                a = fma2(c3.y, xd[q][7], a);
                a = fma2(c4.x, xd[q][8], a);
                a = fma2(c4.y, xd[q][9], a);
                float d0, d1;
                unpack2(a, d0, d1);
                float m = fminf(d0, d1);                 // FMNMX (alu pipe)
                if (m < best[q]) { best[q] = m; bp[q] = p; }  // strict < = first min
            }
        }
    }

    // --- half-1 publishes its per-point results ---
    if (half == 1) {
        #pragma unroll
        for (int q = 0; q < 4; q++) {
            if (q < cnt) {
                sMm[setl][q][lane] = best[q];
                sMb[setl][q][lane] = bp[q];
            }
        }
    }
    __syncthreads();

    // --- half-0 merges (tie -> half 0 = lower k), resolves lane, writes out ---
    float part = 0.f;
    if (half == 0) {
        #pragma unroll
        for (int q = 0; q < 4; q++) {
            if (q < cnt) {
                float m1 = sMm[setl][q][lane];
                int   b1 = sMb[setl][q][lane];
                int p = (m1 < best[q]) ? b1 : bp[q];     // strict: tie keeps half 0

                float d0, d1;
                pair_dists(dims + (size_t)p * 5, esqp[p], xd[q], d0, d1);
                int lsel = (d1 < d0) ? 1 : 0;            // tie -> lane 0 (lower k)
                const float* er = sE + p * PROW;
                float* o = out + (size_t)((wt0 + q) * 32 + lane) * D_DIM;
                #pragma unroll
                for (int j = 0; j < D_DIM; j++) {
                    float qv = er[2 * j + lsel];
                    o[j] = qv;
                    float lo, hi;
                    unpack2(xd[q][j], lo, hi);
                    float xv = -0.5f * lo;               // exact: (-0.5)*(-2x) = x
                    float dd = xv - qv;
                    part += dd * dd;
                }
            }
        }
    }

    // --- deterministic loss: warp reduce -> CTA reduce -> per-CTA partial ---
    #pragma unroll
    for (int offr = 16; offr > 0; offr >>= 1)
        part += __shfl_down_sync(0xFFFFFFFFu, part, offr);
    if (lane == 0) sred[wid] = part;
    __syncthreads();

    if (tid == 0) {
        float s = sred[0] + sred[1] + sred[2] + sred[3];
        g_partials[bid] = s;
        __threadfence();
        unsigned int old = atomicAdd(&g_done, 1u);
        s_last = (old == GRID - 1) ? 1 : 0;
    }
    __syncthreads();

    // --- last CTA finalizes loss (fixed order -> deterministic) ---
    if (s_last) {
        __shared__ float sfin[THREADS];
        float s = 0.f;
        for (int r = tid; r < GRID; r += THREADS)   // fixed strided order
            s += g_partials[r];
        sfin[tid] = s;
        __syncthreads();
        #pragma unroll
        for (int o = THREADS / 2; o > 0; o >>= 1) {
            if (tid < o) sfin[tid] += sfin[tid + o];
            __syncthreads();
        }
        if (tid == 0) {
            out[(size_t)N_PTS * D_DIM] = sfin[0] * (1.0f / ((float)N_PTS * (float)D_DIM));
            g_done = 0;   // reset for next graph replay
        }
    }
}

extern "C" void kernel_launch(void* const* d_in, const int* in_sizes, int n_in,
                              void* d_out, int out_size) {
    const float* x = (const float*)d_in[0];   // encoder_embedding [N, D]
    const float* E = (const float*)d_in[1];   // embedding_weight  [K, D]
    float* out = (float*)d_out;

    vq_kernel<<<GRID, THREADS>>>(x, E, out);
}